// round 14
// baseline (speedup 1.0000x reference)
#include <cuda_runtime.h>
#include <math.h>

// ---------------- problem constants ----------------
#define BB 256
#define NN 4096
#define DD 64
#define KK 16
#define ITERS 3
#define EPS_W 1e-8f
#define LN_EPS 1e-5f
#define SCALE 0.125f   // D^-0.5

typedef unsigned long long u64;

// ---------------- f32x2 packed helpers (FFMA2 is a PTX-only pattern) ----------------
__device__ __forceinline__ u64 ffma2(u64 a, u64 b, u64 c) {
    u64 d;
    asm("fma.rn.f32x2 %0, %1, %2, %3;" : "=l"(d) : "l"(a), "l"(b), "l"(c));
    return d;
}
__device__ __forceinline__ u64 bcast2(float x) {
    u64 r; unsigned xi = __float_as_uint(x);
    asm("mov.b64 %0, {%1, %1};" : "=l"(r) : "r"(xi));
    return r;
}
__device__ __forceinline__ u64 pack2(float x, float y) {
    u64 r;
    asm("mov.b64 %0, {%1, %2};" : "=l"(r) : "r"(__float_as_uint(x)), "r"(__float_as_uint(y)));
    return r;
}
__device__ __forceinline__ float2 unpack2(u64 v) {
    unsigned lo, hi;
    asm("mov.b64 {%0, %1}, %2;" : "=r"(lo), "=r"(hi) : "l"(v));
    return make_float2(__uint_as_float(lo), __uint_as_float(hi));
}

// ---------------- scratch (device globals; no allocation allowed) ----------------
__device__ float g_k[(size_t)BB * NN * DD];      // 256 MB, row-major [b][n][d]
__device__ float g_v[(size_t)BB * NN * DD];      // 256 MB, row-major [b][n][d]
__device__ float g_p[(size_t)BB * KK * NN];      // 67 MB,  [b][k][n] (attn layout)
__device__ float g_slots[BB * KK * DD];
__device__ float g_q[BB * KK * DD];
__device__ float g_U[BB * KK * DD];
__device__ float g_S[BB * KK];

// ---------------- slot init ----------------
__global__ void k_init_slots(const float* __restrict__ mu, const float* __restrict__ lv,
                             const float* __restrict__ noise) {
    int i = blockIdx.x * blockDim.x + threadIdx.x;
    if (i < BB * KK * DD) {
        int e = i & 63;
        g_slots[i] = mu[e] + expf(0.5f * lv[e]) * noise[i];
    }
}

// ---------------- fused LN(inputs) -> k,v projections (v5: 64-row block tile) ----------------
// Block: 64 rows x 128 outputs, 256 threads; thread tile 4 rows x 8 cols =
// 16 u64 accums (~60 regs) -> ~4 blocks/SM = 32 warps NATURALLY (no minBlocks).
// LDS B/FMA ~0.75 (vs R12 0.625, vs failed v4 2x). Weights re-staged per block
// from global: 32KB, L1/L2-resident -> cache traffic, not DRAM.
#define XS 66   // s_x row stride in floats

__global__ __launch_bounds__(256) void k_lnkv(
    const float* __restrict__ x,
    const float* __restrict__ wk, const float* __restrict__ bk,
    const float* __restrict__ wv, const float* __restrict__ bv,
    const float* __restrict__ gin, const float* __restrict__ bin)
{
    __shared__ float s_x[64 * XS];    // 16.9 KB (LN'd input)
    __shared__ float s_w[64 * 128];   // 32 KB  [d][j]: j<64 -> wk col j, j>=64 -> wv col j-64
    __shared__ float s_bias[128];
    int tid = threadIdx.x;

    for (int i = tid; i < 4096; i += 256) {
        int j = i >> 6, d = i & 63;
        s_w[d * 128 + j]      = wk[i];
        s_w[d * 128 + 64 + j] = wv[i];
    }
    if (tid < 64) { s_bias[tid] = bk[tid]; s_bias[64 + tid] = bv[tid]; }

    size_t rowbase = (size_t)blockIdx.x * 64;
    const float2* xg = (const float2*)(x + rowbase * 64);
    for (int i = tid; i < 2048; i += 256) {      // 64 rows x 32 float2
        int row = i >> 5, c = i & 31;
        float2 t = xg[i];
        *(float2*)&s_x[row * XS + c * 2] = t;
    }
    __syncthreads();

    // LayerNorm in place: 4 threads per row (each owns 16 contiguous floats)
    {
        int row = tid >> 2, quad = tid & 3;
        float* xr = &s_x[row * XS + quad * 16];
        float sum = 0.f;
        #pragma unroll
        for (int t = 0; t < 8; t++) { float2 v = *(float2*)&xr[2 * t]; sum += v.x + v.y; }
        sum += __shfl_xor_sync(0xffffffffu, sum, 1);
        sum += __shfl_xor_sync(0xffffffffu, sum, 2);
        float m = sum * (1.f / 64.f);
        float var = 0.f;
        #pragma unroll
        for (int t = 0; t < 8; t++) {
            float2 v = *(float2*)&xr[2 * t];
            float a = v.x - m, b2 = v.y - m;
            var += a * a + b2 * b2;
        }
        var += __shfl_xor_sync(0xffffffffu, var, 1);
        var += __shfl_xor_sync(0xffffffffu, var, 2);
        float rstd = rsqrtf(var * (1.f / 64.f) + LN_EPS);
        const float2* gg = (const float2*)(gin + quad * 16);
        const float2* bb = (const float2*)(bin + quad * 16);
        #pragma unroll
        for (int t = 0; t < 8; t++) {
            float2 v = *(float2*)&xr[2 * t];
            float2 g = gg[t], bo = bb[t];
            v.x = (v.x - m) * rstd * g.x + bo.x;
            v.y = (v.y - m) * rstd * g.y + bo.y;
            *(float2*)&xr[2 * t] = v;
        }
    }
    __syncthreads();

    // GEMM: thread (ty = tid>>4: rows 4ty..4ty+3, txc = tid&15: cols 8txc..8txc+7)
    int ty = tid >> 4, txc = tid & 15;
    int colbase = 8 * txc;
    u64 acc[4][4];
    {
        ulonglong2 b0 = *(const ulonglong2*)&s_bias[colbase];
        ulonglong2 b1 = *(const ulonglong2*)&s_bias[colbase + 4];
        #pragma unroll
        for (int i = 0; i < 4; i++) {
            acc[i][0] = b0.x; acc[i][1] = b0.y;
            acc[i][2] = b1.x; acc[i][3] = b1.y;
        }
    }
    #pragma unroll 4
    for (int d = 0; d < 64; d++) {
        const float* wrow = &s_w[d * 128 + colbase];
        ulonglong2 w0 = *(const ulonglong2*)&wrow[0];   // LDS.128
        ulonglong2 w1 = *(const ulonglong2*)&wrow[4];   // LDS.128
        u64 A[4];
        #pragma unroll
        for (int i = 0; i < 4; i++) A[i] = bcast2(s_x[(4 * ty + i) * XS + d]);
        #pragma unroll
        for (int i = 0; i < 4; i++) {
            acc[i][0] = ffma2(A[i], w0.x, acc[i][0]);
            acc[i][1] = ffma2(A[i], w0.y, acc[i][1]);
            acc[i][2] = ffma2(A[i], w1.x, acc[i][2]);
            acc[i][3] = ffma2(A[i], w1.y, acc[i][3]);
        }
    }
    // store: txc<8 -> k cols [8txc,8txc+8); txc>=8 -> v cols [8txc-64, ...)
    float* base = (txc < 8) ? (g_k + colbase) : (g_v + colbase - 64);
    #pragma unroll
    for (int i = 0; i < 4; i++) {
        size_t r = rowbase + 4 * ty + i;
        ulonglong2* dst = (ulonglong2*)(base + r * 64);
        ulonglong2 t0; t0.x = acc[i][0]; t0.y = acc[i][1];
        ulonglong2 t1; t1.x = acc[i][2]; t1.y = acc[i][3];
        dst[0] = t0;
        dst[1] = t1;
    }
}

// ---------------- q = LN(slots)@wq.T + bq ; zero U,S ----------------
__global__ __launch_bounds__(256) void k_qproj(
    const float* __restrict__ wq, const float* __restrict__ bq,
    const float* __restrict__ gsl, const float* __restrict__ bsl)
{
    __shared__ float s_row[4][64];
    __shared__ float s_ln[4][64];
    __shared__ float s_stat[4][2];
    int tid = threadIdx.x, r = tid >> 6, e = tid & 63;
    int row = blockIdx.x * 4 + r;                  // b*K + k
    s_row[r][e] = g_slots[row * 64 + e];
    g_U[row * 64 + e] = 0.f;
    __syncthreads();
    if (e == 0) {
        float m = 0.f;
        for (int d = 0; d < 64; d++) m += s_row[r][d];
        m *= (1.f / 64.f);
        float v = 0.f;
        for (int d = 0; d < 64; d++) { float t = s_row[r][d] - m; v += t * t; }
        v *= (1.f / 64.f);
        s_stat[r][0] = m; s_stat[r][1] = rsqrtf(v + LN_EPS);
        g_S[row] = 0.f;
    }
    __syncthreads();
    float m = s_stat[r][0], rs = s_stat[r][1];
    s_ln[r][e] = (s_row[r][e] - m) * rs * gsl[e] + bsl[e];
    __syncthreads();
    float acc = bq[e];
    const float4* wrow = (const float4*)(wq + e * 64);
    #pragma unroll
    for (int c = 0; c < 16; c++) {
        float4 w = wrow[c];
        float4 l = *(const float4*)&s_ln[r][c * 4];
        acc = fmaf(l.x, w.x, acc); acc = fmaf(l.y, w.y, acc);
        acc = fmaf(l.z, w.z, acc); acc = fmaf(l.w, w.w, acc);
    }
    g_q[row * 64 + e] = acc;
}

// ---------------- attend kernel A: logits + softmax -> dst[b][k][n] ----------------
// (measured 120us/launch @ 2.7 TB/s -- unchanged)
// dst may be nullptr -> falls back to g_p DEVICE-SIDE (host must never take a
// __device__ symbol's address: R9 NaN bug). NO minBlocks (R4/R6 lesson).
template <bool ADD_EPS>
__global__ __launch_bounds__(256) void k_logits(float* __restrict__ dst)
{
    __shared__ __align__(16) float s_q[16 * 64];   // [s][d]
    float* out = dst ? dst : g_p;                  // device-side symbol ref: legal
    int tid = threadIdx.x;
    int b = blockIdx.y;
    #pragma unroll
    for (int i = 0; i < 4; i++) s_q[tid + 256 * i] = g_q[b * 1024 + tid + 256 * i];
    __syncthreads();

    int n = blockIdx.x * 256 + tid;
    const ulonglong2* kr = (const ulonglong2*)(g_k + ((size_t)b * NN + n) * 64);
    u64 la[16];
    #pragma unroll
    for (int s = 0; s < 16; s++) la[s] = 0ull;
    #pragma unroll
    for (int c = 0; c < 16; c++) {
        ulonglong2 ka = kr[c];
        #pragma unroll
        for (int s = 0; s < 16; s++) {
            ulonglong2 qq = *(const ulonglong2*)(s_q + s * 64 + 4 * c);   // broadcast
            la[s] = ffma2(ka.x, qq.x, la[s]);
            la[s] = ffma2(ka.y, qq.y, la[s]);
        }
    }
    float A[16];
    float mx = -1e30f;
    #pragma unroll
    for (int s = 0; s < 16; s++) {
        float2 t = unpack2(la[s]);
        A[s] = (t.x + t.y) * SCALE;
        mx = fmaxf(mx, A[s]);
    }
    float sum = 0.f;
    #pragma unroll
    for (int s = 0; s < 16; s++) { A[s] = __expf(A[s] - mx); sum += A[s]; }
    float inv = 1.f / sum;
    size_t base = (size_t)b * 16 * NN + n;
    #pragma unroll
    for (int s = 0; s < 16; s++) {
        float p = A[s] * inv;
        if (ADD_EPS) p += EPS_W;
        out[base + (size_t)s * NN] = p;      // coalesced per s
    }
}

// ---------------- attend kernel B: U[k][d] += sum_n p*v ; S[k] += sum_n p ----------------
#define PRS 20   // s_p row stride in floats

__global__ __launch_bounds__(256) void k_update()
{
    __shared__ float s_p[512 * PRS];   // p[n][k]; reused as reduction buffer
    int tid = threadIdx.x;
    int b = blockIdx.y, chunk = blockIdx.x;
    int nbase = chunk * 512;

    // load + transpose p tile; accumulate per-k sum for S
    {
        int kk = tid >> 4, l16 = tid & 15;
        const float* prow = g_p + ((size_t)(b * 16 + kk)) * NN + nbase;
        float psum = 0.f;
        #pragma unroll
        for (int j = 0; j < 8; j++) {
            int n0 = l16 * 4 + j * 64;
            float4 pv = *(const float4*)(prow + n0);     // coalesced LDG.128
            s_p[(n0 + 0) * PRS + kk] = pv.x;
            s_p[(n0 + 1) * PRS + kk] = pv.y;
            s_p[(n0 + 2) * PRS + kk] = pv.z;
            s_p[(n0 + 3) * PRS + kk] = pv.w;
            psum += pv.x + pv.y + pv.z + pv.w;
        }
        psum += __shfl_xor_sync(0xffffffffu, psum, 8);
        psum += __shfl_xor_sync(0xffffffffu, psum, 4);
        psum += __shfl_xor_sync(0xffffffffu, psum, 2);
        psum += __shfl_xor_sync(0xffffffffu, psum, 1);
        if (l16 == 0) atomicAdd(&g_S[b * 16 + kk], psum);
    }
    __syncthreads();

    // ---- phase 2 (measured version, verbatim) ----
    int dg = tid & 15, nsub = tid >> 4;
    u64 u2[8][4];
    #pragma unroll
    for (int kk = 0; kk < 8; kk++)
        #pragma unroll
        for (int j = 0; j < 4; j++) u2[kk][j] = 0ull;

    const float* vbase = g_v + ((size_t)b * NN + nbase) * 64;
    for (int i = 0; i < 32; i++) {
        int n = i * 16 + nsub;
        float4 vv = *(const float4*)(vbase + (size_t)n * 64 + dg * 4);
        u64 v0 = bcast2(vv.x), v1 = bcast2(vv.y), v2 = bcast2(vv.z), v3 = bcast2(vv.w);
        const ulonglong2* pr = (const ulonglong2*)(s_p + n * PRS);
        #pragma unroll
        for (int kk2 = 0; kk2 < 4; kk2++) {
            ulonglong2 pp = pr[kk2];
            u2[2 * kk2][0] = ffma2(pp.x, v0, u2[2 * kk2][0]);
            u2[2 * kk2][1] = ffma2(pp.x, v1, u2[2 * kk2][1]);
            u2[2 * kk2][2] = ffma2(pp.x, v2, u2[2 * kk2][2]);
            u2[2 * kk2][3] = ffma2(pp.x, v3, u2[2 * kk2][3]);
            u2[2 * kk2 + 1][0] = ffma2(pp.y, v0, u2[2 * kk2 + 1][0]);
            u2[2 * kk2 + 1][1] = ffma2(pp.y, v1, u2[2 * kk2 + 1][1]);
            u2[2 * kk2 + 1][2] = ffma2(pp.y, v2, u2[2 * kk2 + 1][2]);
            u2[2 * kk2 + 1][3] = ffma2(pp.y, v3, u2[2 * kk2 + 1][3]);
        }
    }

    // reduce nsub pairs within warp (lane L <-> L^16, same dg)
    #pragma unroll
    for (int kk = 0; kk < 8; kk++) {
        #pragma unroll
        for (int j = 0; j < 4; j++) {
            u64 o = __shfl_xor_sync(0xffffffffu, u2[kk][j], 16);
            float2 a = unpack2(u2[kk][j]), c = unpack2(o);
            a.x += c.x; a.y += c.y;
            u2[kk][j] = pack2(a.x, a.y);
        }
    }

    __syncthreads();               // all s_p reads done -> reuse as s_red
    float* s_red = s_p;            // [8 warps][1024]
    int w = tid >> 5, lane = tid & 31;
    if (lane < 16) {
        float* dstw = s_red + w * 1024;
        #pragma unroll
        for (int kk = 0; kk < 8; kk++) {
            #pragma unroll
            for (int j = 0; j < 4; j++) {
                float2 f = unpack2(u2[kk][j]);
                dstw[(2 * kk) * 64 + dg * 4 + j] = f.x;
                dstw[(2 * kk + 1) * 64 + dg * 4 + j] = f.y;
            }
        }
    }
    __syncthreads();

    float4 r = make_float4(0.f, 0.f, 0.f, 0.f);
    #pragma unroll
    for (int ww = 0; ww < 8; ww++) {
        float4 t = *(const float4*)(s_red + ww * 1024 + tid * 4);
        r.x += t.x; r.y += t.y; r.z += t.z; r.w += t.w;
    }
    float* Ub = g_U + (size_t)b * 1024 + tid * 4;
    atomicAdd(&Ub[0], r.x);
    atomicAdd(&Ub[1], r.y);
    atomicAdd(&Ub[2], r.z);
    atomicAdd(&Ub[3], r.w);
}

// ---------------- GRU cell + LN + MLP residual ----------------
__global__ __launch_bounds__(256) void k_gru_mlp(
    const float* __restrict__ w_ih, const float* __restrict__ w_hh,
    const float* __restrict__ b_ih, const float* __restrict__ b_hh,
    const float* __restrict__ gml, const float* __restrict__ bml,
    const float* __restrict__ w1, const float* __restrict__ b1,
    const float* __restrict__ w2, const float* __restrict__ b2)
{
    __shared__ float s_upd[4][64], s_prev[4][64], s_new[4][64], s_ln[4][64], s_h1[4][128];
    __shared__ float s_stat[4][2];
    int tid = threadIdx.x, r = tid >> 6, e = tid & 63;
    int row = blockIdx.x * 4 + r;
    float Sv = g_S[row];
    s_upd[r][e] = g_U[row * 64 + e] / Sv;
    s_prev[r][e] = g_slots[row * 64 + e];
    __syncthreads();

    float xr = b_ih[e], xz = b_ih[64 + e], xn = b_ih[128 + e];
    float hr = b_hh[e], hz = b_hh[64 + e], hn = b_hh[128 + e];
    const float4* wir = (const float4*)(w_ih + (size_t)e * 64);
    const float4* wiz = (const float4*)(w_ih + (size_t)(64 + e) * 64);
    const float4* win = (const float4*)(w_ih + (size_t)(128 + e) * 64);
    const float4* whr = (const float4*)(w_hh + (size_t)e * 64);
    const float4* whz = (const float4*)(w_hh + (size_t)(64 + e) * 64);
    const float4* whn = (const float4*)(w_hh + (size_t)(128 + e) * 64);
    #pragma unroll
    for (int c = 0; c < 16; c++) {
        float4 u = *(const float4*)&s_upd[r][c * 4];
        float4 p = *(const float4*)&s_prev[r][c * 4];
        float4 w;
        w = wir[c]; xr = fmaf(u.x, w.x, xr); xr = fmaf(u.y, w.y, xr); xr = fmaf(u.z, w.z, xr); xr = fmaf(u.w, w.w, xr);
        w = wiz[c]; xz = fmaf(u.x, w.x, xz); xz = fmaf(u.y, w.y, xz); xz = fmaf(u.z, w.z, xz); xz = fmaf(u.w, w.w, xz);
        w = win[c]; xn = fmaf(u.x, w.x, xn); xn = fmaf(u.y, w.y, xn); xn = fmaf(u.z, w.z, xn); xn = fmaf(u.w, w.w, xn);
        w = whr[c]; hr = fmaf(p.x, w.x, hr); hr = fmaf(p.y, w.y, hr); hr = fmaf(p.z, w.z, hr); hr = fmaf(p.w, w.w, hr);
        w = whz[c]; hz = fmaf(p.x, w.x, hz); hz = fmaf(p.y, w.y, hz); hz = fmaf(p.z, w.z, hz); hz = fmaf(p.w, w.w, hz);
        w = whn[c]; hn = fmaf(p.x, w.x, hn); hn = fmaf(p.y, w.y, hn); hn = fmaf(p.z, w.z, hn); hn = fmaf(p.w, w.w, hn);
    }
    float rg = 1.f / (1.f + expf(-(xr + hr)));
    float zg = 1.f / (1.f + expf(-(xz + hz)));
    float ng = tanhf(xn + rg * hn);
    float sn = (1.f - zg) * ng + zg * s_prev[r][e];
    s_new[r][e] = sn;
    __syncthreads();
    if (e == 0) {
        float m = 0.f;
        for (int d = 0; d < 64; d++) m += s_new[r][d];
        m *= (1.f / 64.f);
        float v = 0.f;
        for (int d = 0; d < 64; d++) { float t = s_new[r][d] - m; v += t * t; }
        v *= (1.f / 64.f);
        s_stat[r][0] = m; s_stat[r][1] = rsqrtf(v + LN_EPS);
    }
    __syncthreads();
    float m = s_stat[r][0], rs = s_stat[r][1];
    s_ln[r][e] = (sn - m) * rs * gml[e] + bml[e];
    __syncthreads();
    #pragma unroll
    for (int t = 0; t < 2; t++) {
        int h = e + 64 * t;
        float a = b1[h];
        const float4* w1r = (const float4*)(w1 + (size_t)h * 64);
        #pragma unroll
        for (int c = 0; c < 16; c++) {
            float4 lv = *(const float4*)&s_ln[r][c * 4];
            float4 w = w1r[c];
            a = fmaf(lv.x, w.x, a); a = fmaf(lv.y, w.y, a);
            a = fmaf(lv.z, w.z, a); a = fmaf(lv.w, w.w, a);
        }
        s_h1[r][h] = fmaxf(a, 0.f);
    }
    __syncthreads();
    float o = b2[e];
    const float4* w2r = (const float4*)(w2 + (size_t)e * 128);
    #pragma unroll
    for (int c = 0; c < 32; c++) {
        float4 h = *(const float4*)&s_h1[r][c * 4];
        float4 w = w2r[c];
        o = fmaf(h.x, w.x, o); o = fmaf(h.y, w.y, o);
        o = fmaf(h.z, w.z, o); o = fmaf(h.w, w.w, o);
    }
    g_slots[row * 64 + e] = sn + o;
}

__global__ void k_copy_slots(float* __restrict__ out) {
    int i = blockIdx.x * blockDim.x + threadIdx.x;
    if (i < BB * KK * DD) out[i] = g_slots[i];
}

// ---------------- launch ----------------
extern "C" void kernel_launch(void* const* d_in, const int* in_sizes, int n_in,
                              void* d_out, int out_size) {
    const float* inputs = (const float*)d_in[0];
    // d_in[1] = mask: all-true and constant over slots -> no-op for slot-axis softmax.
    const float* noise = (const float*)d_in[2];
    const float* mu    = (const float*)d_in[3];
    const float* lv    = (const float*)d_in[4];
    const float* wq = (const float*)d_in[5];  const float* bq = (const float*)d_in[6];
    const float* wk = (const float*)d_in[7];  const float* bk = (const float*)d_in[8];
    const float* wv = (const float*)d_in[9];  const float* bv = (const float*)d_in[10];
    const float* w_ih = (const float*)d_in[11]; const float* w_hh = (const float*)d_in[12];
    const float* b_ih = (const float*)d_in[13]; const float* b_hh = (const float*)d_in[14];
    const float* gin = (const float*)d_in[15]; const float* bin = (const float*)d_in[16];
    const float* gsl = (const float*)d_in[17]; const float* bsl = (const float*)d_in[18];
    const float* gml = (const float*)d_in[19]; const float* bml = (const float*)d_in[20];
    const float* w1 = (const float*)d_in[21]; const float* b1 = (const float*)d_in[22];
    const float* w2 = (const float*)d_in[23]; const float* b2 = (const float*)d_in[24];

    float* out = (float*)d_out;
    const int SZ_SLOTS = BB * KK * DD;
    const int SZ_ATTN  = BB * KK * NN;
    float* out_slots = nullptr;
    float* out_attn  = nullptr;
    if (out_size >= SZ_SLOTS + SZ_ATTN) { out_slots = out; out_attn = out + SZ_SLOTS; }
    else if (out_size >= SZ_ATTN)       { out_attn = out; }
    else                                { out_slots = out; }

    k_init_slots<<<(BB * KK * DD + 255) / 256, 256>>>(mu, lv, noise);
    k_lnkv<<<BB * NN / 64, 256>>>(inputs, wk, bk, wv, bv, gin, bin);

    for (int it = 0; it < ITERS; it++) {
        k_qproj<<<BB * KK / 4, 256>>>(wq, bq, gsl, bsl);
        k_logits<true><<<dim3(16, BB), 256>>>(nullptr);   // nullptr -> g_p (device-side)
        k_update<<<dim3(8, BB), 256>>>();
        k_gru_mlp<<<BB * KK / 4, 256>>>(w_ih, w_hh, b_ih, b_hh, gml, bml, w1, b1, w2, b2);
    }
    k_qproj<<<BB * KK / 4, 256>>>(wq, bq, gsl, bsl);
    // final attn: write directly to harness output if present, else g_p (device fallback)
    k_logits<false><<<dim3(16, BB), 256>>>(out_attn);
    if (out_slots) k_copy_slots<<<(BB * KK * DD + 255) / 256, 256>>>(out_slots);
}

// round 15
// speedup vs baseline: 1.2245x; 1.2245x over previous
#include <cuda_runtime.h>
#include <math.h>

// ---------------- problem constants ----------------
#define BB 256
#define NN 4096
#define DD 64
#define KK 16
#define ITERS 3
#define EPS_W 1e-8f
#define LN_EPS 1e-5f
#define SCALE 0.125f   // D^-0.5

typedef unsigned long long u64;

// ---------------- f32x2 packed helpers (FFMA2 is a PTX-only pattern) ----------------
__device__ __forceinline__ u64 ffma2(u64 a, u64 b, u64 c) {
    u64 d;
    asm("fma.rn.f32x2 %0, %1, %2, %3;" : "=l"(d) : "l"(a), "l"(b), "l"(c));
    return d;
}
__device__ __forceinline__ u64 bcast2(float x) {
    u64 r; unsigned xi = __float_as_uint(x);
    asm("mov.b64 %0, {%1, %1};" : "=l"(r) : "r"(xi));
    return r;
}
__device__ __forceinline__ u64 pack2(float x, float y) {
    u64 r;
    asm("mov.b64 %0, {%1, %2};" : "=l"(r) : "r"(__float_as_uint(x)), "r"(__float_as_uint(y)));
    return r;
}
__device__ __forceinline__ float2 unpack2(u64 v) {
    unsigned lo, hi;
    asm("mov.b64 {%0, %1}, %2;" : "=r"(lo), "=r"(hi) : "l"(v));
    return make_float2(__uint_as_float(lo), __uint_as_float(hi));
}

// ---------------- scratch (device globals; no allocation allowed) ----------------
__device__ float g_k[(size_t)BB * NN * DD];      // 256 MB, row-major [b][n][d]
__device__ float g_v[(size_t)BB * NN * DD];      // 256 MB, row-major [b][n][d]
__device__ float g_p[(size_t)BB * KK * NN];      // 67 MB,  [b][k][n] (attn layout)
__device__ float g_slots[BB * KK * DD];
__device__ float g_q[BB * KK * DD];
__device__ float g_U[BB * KK * DD];
__device__ float g_S[BB * KK];

// ---------------- slot init ----------------
__global__ void k_init_slots(const float* __restrict__ mu, const float* __restrict__ lv,
                             const float* __restrict__ noise) {
    int i = blockIdx.x * blockDim.x + threadIdx.x;
    if (i < BB * KK * DD) {
        int e = i & 63;
        g_slots[i] = mu[e] + expf(0.5f * lv[e]) * noise[i];
    }
}

// ---------------- fused LN(inputs) -> k,v projections (R12 tiled GEMM, verbatim) ----------------
// Best measured lnkv (~830us). Block: 128 rows x 128 outputs; thread tile 4x16.
#define XS 66   // shared row stride in floats

__global__ __launch_bounds__(256, 2) void k_lnkv(
    const float* __restrict__ x,
    const float* __restrict__ wk, const float* __restrict__ bk,
    const float* __restrict__ wv, const float* __restrict__ bv,
    const float* __restrict__ gin, const float* __restrict__ bin)
{
    __shared__ float s_x[128 * XS];   // 33.8 KB (LN'd input)
    __shared__ float s_w[64 * 128];   // 32 KB  [d][j]: j<64 -> wk col j, j>=64 -> wv col j-64
    __shared__ float s_bias[128];
    int tid = threadIdx.x;

    for (int i = tid; i < 4096; i += 256) {
        int j = i >> 6, d = i & 63;
        s_w[d * 128 + j]      = wk[i];
        s_w[d * 128 + 64 + j] = wv[i];
    }
    if (tid < 64) { s_bias[tid] = bk[tid]; s_bias[64 + tid] = bv[tid]; }

    size_t rowbase = (size_t)blockIdx.x * 128;
    const float2* xg = (const float2*)(x + rowbase * 64);
    for (int i = tid; i < 4096; i += 256) {      // 128 rows x 32 float2
        int row = i >> 5, c = i & 31;
        float2 t = xg[i];
        *(float2*)&s_x[row * XS + c * 2] = t;
    }
    __syncthreads();

    // LayerNorm in place: 2 threads per row
    {
        int row = tid >> 1, half = tid & 1;
        float* xr = &s_x[row * XS + half * 32];
        float sum = 0.f;
        #pragma unroll
        for (int t = 0; t < 16; t++) { float2 v = *(float2*)&xr[2 * t]; sum += v.x + v.y; }
        sum += __shfl_xor_sync(0xffffffffu, sum, 1);
        float m = sum * (1.f / 64.f);
        float var = 0.f;
        #pragma unroll
        for (int t = 0; t < 16; t++) {
            float2 v = *(float2*)&xr[2 * t];
            float a = v.x - m, b2 = v.y - m;
            var += a * a + b2 * b2;
        }
        var += __shfl_xor_sync(0xffffffffu, var, 1);
        float rstd = rsqrtf(var * (1.f / 64.f) + LN_EPS);
        const float2* gg = (const float2*)(gin + half * 32);
        const float2* bb = (const float2*)(bin + half * 32);
        #pragma unroll
        for (int t = 0; t < 16; t++) {
            float2 v = *(float2*)&xr[2 * t];
            float2 g = gg[t], bo = bb[t];
            v.x = (v.x - m) * rstd * g.x + bo.x;
            v.y = (v.y - m) * rstd * g.y + bo.y;
            *(float2*)&xr[2 * t] = v;
        }
    }
    __syncthreads();

    // GEMM: thread (ty = tid>>3: rows 4ty..4ty+3, tx = tid&7: cols {16m + 2tx, +1})
    int ty = tid >> 3, tx = tid & 7;
    u64 acc[4][8];
    #pragma unroll
    for (int m = 0; m < 8; m++) {
        u64 bb = *(const u64*)&s_bias[16 * m + 2 * tx];
        acc[0][m] = bb; acc[1][m] = bb; acc[2][m] = bb; acc[3][m] = bb;
    }
    #pragma unroll 4
    for (int d = 0; d < 64; d++) {
        u64 A[4];
        #pragma unroll
        for (int i = 0; i < 4; i++) A[i] = bcast2(s_x[(4 * ty + i) * XS + d]);
        #pragma unroll
        for (int m = 0; m < 8; m++) {
            u64 w = *(const u64*)&s_w[d * 128 + 16 * m + 2 * tx];
            acc[0][m] = ffma2(A[0], w, acc[0][m]);
            acc[1][m] = ffma2(A[1], w, acc[1][m]);
            acc[2][m] = ffma2(A[2], w, acc[2][m]);
            acc[3][m] = ffma2(A[3], w, acc[3][m]);
        }
    }
    #pragma unroll
    for (int i = 0; i < 4; i++) {
        size_t r = rowbase + 4 * ty + i;
        u64* dk = (u64*)(g_k + r * 64);
        u64* dv = (u64*)(g_v + r * 64);
        #pragma unroll
        for (int m = 0; m < 4; m++) {
            dk[8 * m + tx] = acc[i][m];
            dv[8 * m + tx] = acc[i][4 + m];
        }
    }
}

// ---------------- q = LN(slots)@wq.T + bq ; zero U,S ----------------
__global__ __launch_bounds__(256) void k_qproj(
    const float* __restrict__ wq, const float* __restrict__ bq,
    const float* __restrict__ gsl, const float* __restrict__ bsl)
{
    __shared__ float s_row[4][64];
    __shared__ float s_ln[4][64];
    __shared__ float s_stat[4][2];
    int tid = threadIdx.x, r = tid >> 6, e = tid & 63;
    int row = blockIdx.x * 4 + r;                  // b*K + k
    s_row[r][e] = g_slots[row * 64 + e];
    g_U[row * 64 + e] = 0.f;
    __syncthreads();
    if (e == 0) {
        float m = 0.f;
        for (int d = 0; d < 64; d++) m += s_row[r][d];
        m *= (1.f / 64.f);
        float v = 0.f;
        for (int d = 0; d < 64; d++) { float t = s_row[r][d] - m; v += t * t; }
        v *= (1.f / 64.f);
        s_stat[r][0] = m; s_stat[r][1] = rsqrtf(v + LN_EPS);
        g_S[row] = 0.f;
    }
    __syncthreads();
    float m = s_stat[r][0], rs = s_stat[r][1];
    s_ln[r][e] = (s_row[r][e] - m) * rs * gsl[e] + bsl[e];
    __syncthreads();
    float acc = bq[e];
    const float4* wrow = (const float4*)(wq + e * 64);
    #pragma unroll
    for (int c = 0; c < 16; c++) {
        float4 w = wrow[c];
        float4 l = *(const float4*)&s_ln[r][c * 4];
        acc = fmaf(l.x, w.x, acc); acc = fmaf(l.y, w.y, acc);
        acc = fmaf(l.z, w.z, acc); acc = fmaf(l.w, w.w, acc);
    }
    g_q[row * 64 + e] = acc;
}

// ---------------- attend kernel A v2: smem-staged k -> logits + softmax ----------------
// Block: 128 threads, 128 n. k tile staged COALESCED into s_k[128][66] (8x fewer
// L1 wavefronts than the 256B-stride per-lane LDG.128 of v1), compute from LDS.
// dst nullptr -> g_p device-side (R9 lesson). NO minBlocks (R4/R6 lesson).
template <bool ADD_EPS>
__global__ __launch_bounds__(128) void k_logits(float* __restrict__ dst)
{
    __shared__ __align__(16) float s_q[16 * 64];   // [s][d], 4 KB
    __shared__ __align__(16) float s_k[128 * XS];  // 33.8 KB
    float* out = dst ? dst : g_p;                  // device-side symbol ref: legal
    int tid = threadIdx.x;
    int b = blockIdx.y;
    int nbase = blockIdx.x * 128;

    #pragma unroll
    for (int i = 0; i < 8; i++) s_q[tid + 128 * i] = g_q[b * 1024 + tid + 128 * i];

    const float2* kg = (const float2*)(g_k + ((size_t)b * NN + nbase) * 64);
    for (int i = tid; i < 4096; i += 128) {        // 128 rows x 32 float2, coalesced
        int row = i >> 5, c = i & 31;
        *(float2*)&s_k[row * XS + c * 2] = kg[i];
    }
    __syncthreads();

    const float* krow = &s_k[tid * XS];
    u64 la[16];
    #pragma unroll
    for (int s = 0; s < 16; s++) la[s] = 0ull;
    #pragma unroll
    for (int c = 0; c < 16; c++) {
        u64 ka0 = *(const u64*)&krow[4 * c];       // LDS.64, ~2-way conflict
        u64 ka1 = *(const u64*)&krow[4 * c + 2];
        #pragma unroll
        for (int s = 0; s < 16; s++) {
            ulonglong2 qq = *(const ulonglong2*)(s_q + s * 64 + 4 * c);   // broadcast
            la[s] = ffma2(ka0, qq.x, la[s]);
            la[s] = ffma2(ka1, qq.y, la[s]);
        }
    }
    float A[16];
    float mx = -1e30f;
    #pragma unroll
    for (int s = 0; s < 16; s++) {
        float2 t = unpack2(la[s]);
        A[s] = (t.x + t.y) * SCALE;
        mx = fmaxf(mx, A[s]);
    }
    float sum = 0.f;
    #pragma unroll
    for (int s = 0; s < 16; s++) { A[s] = __expf(A[s] - mx); sum += A[s]; }
    float inv = 1.f / sum;
    size_t base = (size_t)b * 16 * NN + nbase + tid;
    #pragma unroll
    for (int s = 0; s < 16; s++) {
        float p = A[s] * inv;
        if (ADD_EPS) p += EPS_W;
        out[base + (size_t)s * NN] = p;            // coalesced per s
    }
}

// ---------------- attend kernel B: U[k][d] += sum_n p*v ; S[k] += sum_n p ----------------
#define PRS 20   // s_p row stride in floats

__global__ __launch_bounds__(256) void k_update()
{
    __shared__ float s_p[512 * PRS];   // p[n][k]; reused as reduction buffer
    int tid = threadIdx.x;
    int b = blockIdx.y, chunk = blockIdx.x;
    int nbase = chunk * 512;

    // load + transpose p tile; accumulate per-k sum for S
    {
        int kk = tid >> 4, l16 = tid & 15;
        const float* prow = g_p + ((size_t)(b * 16 + kk)) * NN + nbase;
        float psum = 0.f;
        #pragma unroll
        for (int j = 0; j < 8; j++) {
            int n0 = l16 * 4 + j * 64;
            float4 pv = *(const float4*)(prow + n0);     // coalesced LDG.128
            s_p[(n0 + 0) * PRS + kk] = pv.x;
            s_p[(n0 + 1) * PRS + kk] = pv.y;
            s_p[(n0 + 2) * PRS + kk] = pv.z;
            s_p[(n0 + 3) * PRS + kk] = pv.w;
            psum += pv.x + pv.y + pv.z + pv.w;
        }
        psum += __shfl_xor_sync(0xffffffffu, psum, 8);
        psum += __shfl_xor_sync(0xffffffffu, psum, 4);
        psum += __shfl_xor_sync(0xffffffffu, psum, 2);
        psum += __shfl_xor_sync(0xffffffffu, psum, 1);
        if (l16 == 0) atomicAdd(&g_S[b * 16 + kk], psum);
    }
    __syncthreads();

    // ---- phase 2 (measured version, verbatim) ----
    int dg = tid & 15, nsub = tid >> 4;
    u64 u2[8][4];
    #pragma unroll
    for (int kk = 0; kk < 8; kk++)
        #pragma unroll
        for (int j = 0; j < 4; j++) u2[kk][j] = 0ull;

    const float* vbase = g_v + ((size_t)b * NN + nbase) * 64;
    for (int i = 0; i < 32; i++) {
        int n = i * 16 + nsub;
        float4 vv = *(const float4*)(vbase + (size_t)n * 64 + dg * 4);
        u64 v0 = bcast2(vv.x), v1 = bcast2(vv.y), v2 = bcast2(vv.z), v3 = bcast2(vv.w);
        const ulonglong2* pr = (const ulonglong2*)(s_p + n * PRS);
        #pragma unroll
        for (int kk2 = 0; kk2 < 4; kk2++) {
            ulonglong2 pp = pr[kk2];
            u2[2 * kk2][0] = ffma2(pp.x, v0, u2[2 * kk2][0]);
            u2[2 * kk2][1] = ffma2(pp.x, v1, u2[2 * kk2][1]);
            u2[2 * kk2][2] = ffma2(pp.x, v2, u2[2 * kk2][2]);
            u2[2 * kk2][3] = ffma2(pp.x, v3, u2[2 * kk2][3]);
            u2[2 * kk2 + 1][0] = ffma2(pp.y, v0, u2[2 * kk2 + 1][0]);
            u2[2 * kk2 + 1][1] = ffma2(pp.y, v1, u2[2 * kk2 + 1][1]);
            u2[2 * kk2 + 1][2] = ffma2(pp.y, v2, u2[2 * kk2 + 1][2]);
            u2[2 * kk2 + 1][3] = ffma2(pp.y, v3, u2[2 * kk2 + 1][3]);
        }
    }

    // reduce nsub pairs within warp (lane L <-> L^16, same dg)
    #pragma unroll
    for (int kk = 0; kk < 8; kk++) {
        #pragma unroll
        for (int j = 0; j < 4; j++) {
            u64 o = __shfl_xor_sync(0xffffffffu, u2[kk][j], 16);
            float2 a = unpack2(u2[kk][j]), c = unpack2(o);
            a.x += c.x; a.y += c.y;
            u2[kk][j] = pack2(a.x, a.y);
        }
    }

    __syncthreads();               // all s_p reads done -> reuse as s_red
    float* s_red = s_p;            // [8 warps][1024]
    int w = tid >> 5, lane = tid & 31;
    if (lane < 16) {
        float* dstw = s_red + w * 1024;
        #pragma unroll
        for (int kk = 0; kk < 8; kk++) {
            #pragma unroll
            for (int j = 0; j < 4; j++) {
                float2 f = unpack2(u2[kk][j]);
                dstw[(2 * kk) * 64 + dg * 4 + j] = f.x;
                dstw[(2 * kk + 1) * 64 + dg * 4 + j] = f.y;
            }
        }
    }
    __syncthreads();

    float4 r = make_float4(0.f, 0.f, 0.f, 0.f);
    #pragma unroll
    for (int ww = 0; ww < 8; ww++) {
        float4 t = *(const float4*)(s_red + ww * 1024 + tid * 4);
        r.x += t.x; r.y += t.y; r.z += t.z; r.w += t.w;
    }
    float* Ub = g_U + (size_t)b * 1024 + tid * 4;
    atomicAdd(&Ub[0], r.x);
    atomicAdd(&Ub[1], r.y);
    atomicAdd(&Ub[2], r.z);
    atomicAdd(&Ub[3], r.w);
}

// ---------------- GRU cell + LN + MLP residual ----------------
__global__ __launch_bounds__(256) void k_gru_mlp(
    const float* __restrict__ w_ih, const float* __restrict__ w_hh,
    const float* __restrict__ b_ih, const float* __restrict__ b_hh,
    const float* __restrict__ gml, const float* __restrict__ bml,
    const float* __restrict__ w1, const float* __restrict__ b1,
    const float* __restrict__ w2, const float* __restrict__ b2)
{
    __shared__ float s_upd[4][64], s_prev[4][64], s_new[4][64], s_ln[4][64], s_h1[4][128];
    __shared__ float s_stat[4][2];
    int tid = threadIdx.x, r = tid >> 6, e = tid & 63;
    int row = blockIdx.x * 4 + r;
    float Sv = g_S[row];
    s_upd[r][e] = g_U[row * 64 + e] / Sv;
    s_prev[r][e] = g_slots[row * 64 + e];
    __syncthreads();

    float xr = b_ih[e], xz = b_ih[64 + e], xn = b_ih[128 + e];
    float hr = b_hh[e], hz = b_hh[64 + e], hn = b_hh[128 + e];
    const float4* wir = (const float4*)(w_ih + (size_t)e * 64);
    const float4* wiz = (const float4*)(w_ih + (size_t)(64 + e) * 64);
    const float4* win = (const float4*)(w_ih + (size_t)(128 + e) * 64);
    const float4* whr = (const float4*)(w_hh + (size_t)e * 64);
    const float4* whz = (const float4*)(w_hh + (size_t)(64 + e) * 64);
    const float4* whn = (const float4*)(w_hh + (size_t)(128 + e) * 64);
    #pragma unroll
    for (int c = 0; c < 16; c++) {
        float4 u = *(const float4*)&s_upd[r][c * 4];
        float4 p = *(const float4*)&s_prev[r][c * 4];
        float4 w;
        w = wir[c]; xr = fmaf(u.x, w.x, xr); xr = fmaf(u.y, w.y, xr); xr = fmaf(u.z, w.z, xr); xr = fmaf(u.w, w.w, xr);
        w = wiz[c]; xz = fmaf(u.x, w.x, xz); xz = fmaf(u.y, w.y, xz); xz = fmaf(u.z, w.z, xz); xz = fmaf(u.w, w.w, xz);
        w = win[c]; xn = fmaf(u.x, w.x, xn); xn = fmaf(u.y, w.y, xn); xn = fmaf(u.z, w.z, xn); xn = fmaf(u.w, w.w, xn);
        w = whr[c]; hr = fmaf(p.x, w.x, hr); hr = fmaf(p.y, w.y, hr); hr = fmaf(p.z, w.z, hr); hr = fmaf(p.w, w.w, hr);
        w = whz[c]; hz = fmaf(p.x, w.x, hz); hz = fmaf(p.y, w.y, hz); hz = fmaf(p.z, w.z, hz); hz = fmaf(p.w, w.w, hz);
        w = whn[c]; hn = fmaf(p.x, w.x, hn); hn = fmaf(p.y, w.y, hn); hn = fmaf(p.z, w.z, hn); hn = fmaf(p.w, w.w, hn);
    }
    float rg = 1.f / (1.f + expf(-(xr + hr)));
    float zg = 1.f / (1.f + expf(-(xz + hz)));
    float ng = tanhf(xn + rg * hn);
    float sn = (1.f - zg) * ng + zg * s_prev[r][e];
    s_new[r][e] = sn;
    __syncthreads();
    if (e == 0) {
        float m = 0.f;
        for (int d = 0; d < 64; d++) m += s_new[r][d];
        m *= (1.f / 64.f);
        float v = 0.f;
        for (int d = 0; d < 64; d++) { float t = s_new[r][d] - m; v += t * t; }
        v *= (1.f / 64.f);
        s_stat[r][0] = m; s_stat[r][1] = rsqrtf(v + LN_EPS);
    }
    __syncthreads();
    float m = s_stat[r][0], rs = s_stat[r][1];
    s_ln[r][e] = (sn - m) * rs * gml[e] + bml[e];
    __syncthreads();
    #pragma unroll
    for (int t = 0; t < 2; t++) {
        int h = e + 64 * t;
        float a = b1[h];
        const float4* w1r = (const float4*)(w1 + (size_t)h * 64);
        #pragma unroll
        for (int c = 0; c < 16; c++) {
            float4 lv = *(const float4*)&s_ln[r][c * 4];
            float4 w = w1r[c];
            a = fmaf(lv.x, w.x, a); a = fmaf(lv.y, w.y, a);
            a = fmaf(lv.z, w.z, a); a = fmaf(lv.w, w.w, a);
        }
        s_h1[r][h] = fmaxf(a, 0.f);
    }
    __syncthreads();
    float o = b2[e];
    const float4* w2r = (const float4*)(w2 + (size_t)e * 128);
    #pragma unroll
    for (int c = 0; c < 32; c++) {
        float4 h = *(const float4*)&s_h1[r][c * 4];
        float4 w = w2r[c];
        o = fmaf(h.x, w.x, o); o = fmaf(h.y, w.y, o);
        o = fmaf(h.z, w.z, o); o = fmaf(h.w, w.w, o);
    }
    g_slots[row * 64 + e] = sn + o;
}

__global__ void k_copy_slots(float* __restrict__ out) {
    int i = blockIdx.x * blockDim.x + threadIdx.x;
    if (i < BB * KK * DD) out[i] = g_slots[i];
}

// ---------------- launch ----------------
extern "C" void kernel_launch(void* const* d_in, const int* in_sizes, int n_in,
                              void* d_out, int out_size) {
    const float* inputs = (const float*)d_in[0];
    // d_in[1] = mask: all-true and constant over slots -> no-op for slot-axis softmax.
    const float* noise = (const float*)d_in[2];
    const float* mu    = (const float*)d_in[3];
    const float* lv    = (const float*)d_in[4];
    const float* wq = (const float*)d_in[5];  const float* bq = (const float*)d_in[6];
    const float* wk = (const float*)d_in[7];  const float* bk = (const float*)d_in[8];
    const float* wv = (const float*)d_in[9];  const float* bv = (const float*)d_in[10];
    const float* w_ih = (const float*)d_in[11]; const float* w_hh = (const float*)d_in[12];
    const float* b_ih = (const float*)d_in[13]; const float* b_hh = (const float*)d_in[14];
    const float* gin = (const float*)d_in[15]; const float* bin = (const float*)d_in[16];
    const float* gsl = (const float*)d_in[17]; const float* bsl = (const float*)d_in[18];
    const float* gml = (const float*)d_in[19]; const float* bml = (const float*)d_in[20];
    const float* w1 = (const float*)d_in[21]; const float* b1 = (const float*)d_in[22];
    const float* w2 = (const float*)d_in[23]; const float* b2 = (const float*)d_in[24];

    float* out = (float*)d_out;
    const int SZ_SLOTS = BB * KK * DD;
    const int SZ_ATTN  = BB * KK * NN;
    float* out_slots = nullptr;
    float* out_attn  = nullptr;
    if (out_size >= SZ_SLOTS + SZ_ATTN) { out_slots = out; out_attn = out + SZ_SLOTS; }
    else if (out_size >= SZ_ATTN)       { out_attn = out; }
    else                                { out_slots = out; }

    k_init_slots<<<(BB * KK * DD + 255) / 256, 256>>>(mu, lv, noise);
    k_lnkv<<<BB * NN / 128, 256>>>(inputs, wk, bk, wv, bv, gin, bin);

    for (int it = 0; it < ITERS; it++) {
        k_qproj<<<BB * KK / 4, 256>>>(wq, bq, gsl, bsl);
        k_logits<true><<<dim3(32, BB), 128>>>(nullptr);   // nullptr -> g_p (device-side)
        k_update<<<dim3(8, BB), 256>>>();
        k_gru_mlp<<<BB * KK / 4, 256>>>(w_ih, w_hh, b_ih, b_hh, gml, bml, w1, b1, w2, b2);
    }
    k_qproj<<<BB * KK / 4, 256>>>(wq, bq, gsl, bsl);
    // final attn: write directly to harness output if present, else g_p (device fallback)
    k_logits<false><<<dim3(32, BB), 128>>>(out_attn);
    if (out_slots) k_copy_slots<<<(BB * KK * DD + 255) / 256, 256>>>(out_slots);
}